// round 1
// baseline (speedup 1.0000x reference)
#include <cuda_runtime.h>
#include <math.h>
#include <stddef.h>

// Problem dimensions (fixed by the reference)
#define Bz   4
#define Sz   2048
#define Dz   1024
#define Hz   16
#define DKz  64
#define DFFz 4096
#define Mz   (Bz * Sz)   // 8192 rows

// ---------------------------------------------------------------------------
// Scratch buffers (device globals: no allocation allowed in kernel_launch)
// ---------------------------------------------------------------------------
static __device__ float g_h1[(size_t)Mz * Dz];   // LN1 output
static __device__ float g_q [(size_t)Mz * Dz];
static __device__ float g_k [(size_t)Mz * Dz];
static __device__ float g_v [(size_t)Mz * Dz];
static __device__ float g_at[(size_t)Mz * Dz];   // attention output
static __device__ float g_x2[(size_t)Mz * Dz];   // residual-1 output
static __device__ float g_h2[(size_t)Mz * Dz];   // LN2 output
static __device__ float g_f1[(size_t)Mz * DFFz]; // gelu(h2@w1+b1)

// ---------------------------------------------------------------------------
// LayerNorm: one block per row of 1024, 256 threads, float4 per thread
// ---------------------------------------------------------------------------
__global__ __launch_bounds__(256)
void ln_kernel(const float* __restrict__ x, const float* __restrict__ g,
               const float* __restrict__ bt, float* __restrict__ out)
{
    const int row = blockIdx.x;
    const int tid = threadIdx.x;
    const float4* xr = (const float4*)(x + (size_t)row * Dz);
    float4 v = xr[tid];

    float s  = v.x + v.y + v.z + v.w;
    float s2 = v.x * v.x + v.y * v.y + v.z * v.z + v.w * v.w;

    // warp reduce
    #pragma unroll
    for (int o = 16; o > 0; o >>= 1) {
        s  += __shfl_xor_sync(0xffffffffu, s,  o);
        s2 += __shfl_xor_sync(0xffffffffu, s2, o);
    }
    __shared__ float ws[8], ws2[8];
    const int wid = tid >> 5, lane = tid & 31;
    if (lane == 0) { ws[wid] = s; ws2[wid] = s2; }
    __syncthreads();
    __shared__ float s_mean, s_inv;
    if (tid == 0) {
        float a = 0.f, b = 0.f;
        #pragma unroll
        for (int i = 0; i < 8; i++) { a += ws[i]; b += ws2[i]; }
        float mean = a * (1.0f / Dz);
        float var  = b * (1.0f / Dz) - mean * mean;
        s_mean = mean;
        s_inv  = rsqrtf(var + 1e-5f);
    }
    __syncthreads();
    const float mean = s_mean, inv = s_inv;

    float4 gg = ((const float4*)g)[tid];
    float4 bb = ((const float4*)bt)[tid];
    float4 o;
    o.x = (v.x - mean) * inv * gg.x + bb.x;
    o.y = (v.y - mean) * inv * gg.y + bb.y;
    o.z = (v.z - mean) * inv * gg.z + bb.z;
    o.w = (v.w - mean) * inv * gg.w + bb.w;
    ((float4*)(out + (size_t)row * Dz))[tid] = o;
}

// ---------------------------------------------------------------------------
// SGEMM: C[M,N] = A[M,K] @ B[K,N]  (+bias[N]) (gelu) (+res[M,N])
// 128x128 tile, BK=16, 256 threads, 8x8 per thread (split 4+4 layout)
// ---------------------------------------------------------------------------
__device__ __forceinline__ float gelu_exact(float x)
{
    return 0.5f * x * (1.0f + erff(x * 0.70710678118654752440f));
}

template <bool GELU, bool BIAS, bool RES>
__global__ __launch_bounds__(256)
void sgemm_kernel(const float* __restrict__ A, const float* __restrict__ Bm,
                  const float* __restrict__ bias, const float* __restrict__ res,
                  float* __restrict__ C, int Mi, int Ni, int Ki)
{
    const int BK = 16;
    __shared__ __align__(16) float As[BK][132]; // [k][m], padded
    __shared__ __align__(16) float Bs[BK][132]; // [k][n], padded

    const int tid = threadIdx.x;
    const int bm = blockIdx.y * 128;
    const int bn = blockIdx.x * 128;
    const int tx = tid & 15;   // 0..15 (column group)
    const int ty = tid >> 4;   // 0..15 (row group)

    // load indices
    const int aRow = tid >> 2;          // 0..63
    const int aCol = (tid & 3) * 4;     // 0,4,8,12
    const int bRow = tid >> 5;          // 0..7
    const int bCol = (tid & 31) * 4;    // 0..124

    const float* Ap0 = A + (size_t)(bm + aRow) * Ki + aCol;
    const float* Ap1 = A + (size_t)(bm + aRow + 64) * Ki + aCol;
    const float* Bp  = Bm + (size_t)bRow * Ni + bn + bCol;

    float acc[8][8];
    #pragma unroll
    for (int i = 0; i < 8; i++)
        #pragma unroll
        for (int j = 0; j < 8; j++) acc[i][j] = 0.f;

    for (int k0 = 0; k0 < Ki; k0 += BK) {
        float4 a0 = *(const float4*)(Ap0 + k0);
        float4 a1 = *(const float4*)(Ap1 + k0);
        float4 b0 = *(const float4*)(Bp + (size_t)k0 * Ni);
        float4 b1 = *(const float4*)(Bp + (size_t)(k0 + 8) * Ni);

        As[aCol + 0][aRow] = a0.x; As[aCol + 1][aRow] = a0.y;
        As[aCol + 2][aRow] = a0.z; As[aCol + 3][aRow] = a0.w;
        As[aCol + 0][aRow + 64] = a1.x; As[aCol + 1][aRow + 64] = a1.y;
        As[aCol + 2][aRow + 64] = a1.z; As[aCol + 3][aRow + 64] = a1.w;
        *(float4*)&Bs[bRow][bCol]     = b0;
        *(float4*)&Bs[bRow + 8][bCol] = b1;
        __syncthreads();

        #pragma unroll
        for (int k = 0; k < BK; k++) {
            float ra[8], rb[8];
            *(float4*)&ra[0] = *(const float4*)&As[k][ty * 4];
            *(float4*)&ra[4] = *(const float4*)&As[k][64 + ty * 4];
            *(float4*)&rb[0] = *(const float4*)&Bs[k][tx * 4];
            *(float4*)&rb[4] = *(const float4*)&Bs[k][64 + tx * 4];
            #pragma unroll
            for (int i = 0; i < 8; i++)
                #pragma unroll
                for (int j = 0; j < 8; j++)
                    acc[i][j] = fmaf(ra[i], rb[j], acc[i][j]);
        }
        __syncthreads();
    }

    // epilogue
    #pragma unroll
    for (int ih = 0; ih < 2; ih++) {
        #pragma unroll
        for (int i = 0; i < 4; i++) {
            const int r = bm + ih * 64 + ty * 4 + i;
            #pragma unroll
            for (int jh = 0; jh < 2; jh++) {
                const int cb = bn + jh * 64 + tx * 4;
                float4 o;
                o.x = acc[ih * 4 + i][jh * 4 + 0];
                o.y = acc[ih * 4 + i][jh * 4 + 1];
                o.z = acc[ih * 4 + i][jh * 4 + 2];
                o.w = acc[ih * 4 + i][jh * 4 + 3];
                if (BIAS) {
                    float4 bb = *(const float4*)&bias[cb];
                    o.x += bb.x; o.y += bb.y; o.z += bb.z; o.w += bb.w;
                }
                if (GELU) {
                    o.x = gelu_exact(o.x); o.y = gelu_exact(o.y);
                    o.z = gelu_exact(o.z); o.w = gelu_exact(o.w);
                }
                if (RES) {
                    float4 rr = *(const float4*)&res[(size_t)r * Ni + cb];
                    o.x += rr.x; o.y += rr.y; o.z += rr.z; o.w += rr.w;
                }
                *(float4*)&C[(size_t)r * Ni + cb] = o;
            }
        }
    }
}

// ---------------------------------------------------------------------------
// Causal flash attention, fp32.
// Layout: q/k/v are [B*S, D] where column = h*64 + d  (i.e. [B,S,H,DK]).
// Grid: (S/64, B*H). Block: 64 threads; each thread owns one query row.
// K/V tiles (64x64) staged in shared; q and output accumulator in registers.
// ---------------------------------------------------------------------------
__global__ __launch_bounds__(64)
void attn_kernel(const float* __restrict__ Q, const float* __restrict__ K,
                 const float* __restrict__ V, float* __restrict__ O)
{
    const int qt  = blockIdx.x;        // query tile 0..31
    const int bh  = blockIdx.y;        // 0..63
    const int b   = bh / Hz;
    const int h   = bh % Hz;
    const int tid = threadIdx.x;       // 0..63
    const int sq  = qt * 64 + tid;     // global query position

    __shared__ __align__(16) float4 Ks[64][16];
    __shared__ __align__(16) float4 Vs[64][16];

    // load q row into registers, pre-scaled by 1/sqrt(DK)
    float qr[64];
    {
        const float4* qrow =
            (const float4*)(Q + ((size_t)(b * Sz + sq)) * Dz + h * DKz);
        const float scale = 0.125f; // 1/sqrt(64)
        #pragma unroll
        for (int i = 0; i < 16; i++) {
            float4 t = qrow[i];
            qr[4 * i + 0] = t.x * scale; qr[4 * i + 1] = t.y * scale;
            qr[4 * i + 2] = t.z * scale; qr[4 * i + 3] = t.w * scale;
        }
    }

    float out[64];
    #pragma unroll
    for (int i = 0; i < 64; i++) out[i] = 0.f;
    float m = -INFINITY, l = 0.f;

    for (int kt = 0; kt <= qt; kt++) {
        // cooperative tile load: 64x64 K and V
        #pragma unroll
        for (int it = 0; it < 16; it++) {
            const int idx = it * 64 + tid;
            const int j = idx >> 4, c = idx & 15;
            const size_t gofs =
                ((size_t)(b * Sz + kt * 64 + j)) * Dz + h * DKz + c * 4;
            Ks[j][c] = *(const float4*)(K + gofs);
            Vs[j][c] = *(const float4*)(V + gofs);
        }
        __syncthreads();

        const bool diag = (kt == qt);

        #pragma unroll 1
        for (int j0 = 0; j0 < 64; j0 += 8) {
            float s[8];
            // scores for 8 keys
            #pragma unroll
            for (int jj = 0; jj < 8; jj++) {
                const float4* kr = Ks[j0 + jj];
                float ax = 0.f, ay = 0.f, az = 0.f, aw = 0.f;
                #pragma unroll
                for (int c = 0; c < 16; c++) {
                    float4 kv = kr[c];
                    ax = fmaf(qr[4 * c + 0], kv.x, ax);
                    ay = fmaf(qr[4 * c + 1], kv.y, ay);
                    az = fmaf(qr[4 * c + 2], kv.z, az);
                    aw = fmaf(qr[4 * c + 3], kv.w, aw);
                }
                s[jj] = (ax + ay) + (az + aw);
                if (diag && (j0 + jj) > tid) s[jj] = -INFINITY;
            }
            // online softmax update
            float mt = m;
            #pragma unroll
            for (int jj = 0; jj < 8; jj++) mt = fmaxf(mt, s[jj]);
            const float corr = __expf(m - mt); // 0 if m was -inf
            m = mt;
            l *= corr;
            #pragma unroll
            for (int dd = 0; dd < 64; dd++) out[dd] *= corr;
            #pragma unroll
            for (int jj = 0; jj < 8; jj++) {
                const float p = __expf(s[jj] - m);
                l += p;
                const float4* vr = Vs[j0 + jj];
                #pragma unroll
                for (int c = 0; c < 16; c++) {
                    float4 vv = vr[c];
                    out[4 * c + 0] = fmaf(p, vv.x, out[4 * c + 0]);
                    out[4 * c + 1] = fmaf(p, vv.y, out[4 * c + 1]);
                    out[4 * c + 2] = fmaf(p, vv.z, out[4 * c + 2]);
                    out[4 * c + 3] = fmaf(p, vv.w, out[4 * c + 3]);
                }
            }
        }
        __syncthreads();
    }

    const float inv = 1.0f / l;
    float4* orow = (float4*)(O + ((size_t)(b * Sz + sq)) * Dz + h * DKz);
    #pragma unroll
    for (int i = 0; i < 16; i++) {
        float4 o;
        o.x = out[4 * i + 0] * inv; o.y = out[4 * i + 1] * inv;
        o.z = out[4 * i + 2] * inv; o.w = out[4 * i + 3] * inv;
        orow[i] = o;
    }
}

// ---------------------------------------------------------------------------
// Launcher
// ---------------------------------------------------------------------------
extern "C" void kernel_launch(void* const* d_in, const int* in_sizes, int n_in,
                              void* d_out, int out_size)
{
    (void)in_sizes; (void)n_in; (void)out_size;

    const float* x   = (const float*)d_in[0];
    const float* wq  = (const float*)d_in[1];
    const float* wk  = (const float*)d_in[2];
    const float* wv  = (const float*)d_in[3];
    const float* wo  = (const float*)d_in[4];
    const float* bo  = (const float*)d_in[5];
    const float* w1  = (const float*)d_in[6];
    const float* b1  = (const float*)d_in[7];
    const float* w2  = (const float*)d_in[8];
    const float* b2  = (const float*)d_in[9];
    const float* g1  = (const float*)d_in[10];
    const float* be1 = (const float*)d_in[11];
    const float* g2  = (const float*)d_in[12];
    const float* be2 = (const float*)d_in[13];
    float* out = (float*)d_out;

    float *h1, *q, *k, *v, *at, *x2, *h2, *f1;
    cudaGetSymbolAddress((void**)&h1, g_h1);
    cudaGetSymbolAddress((void**)&q,  g_q);
    cudaGetSymbolAddress((void**)&k,  g_k);
    cudaGetSymbolAddress((void**)&v,  g_v);
    cudaGetSymbolAddress((void**)&at, g_at);
    cudaGetSymbolAddress((void**)&x2, g_x2);
    cudaGetSymbolAddress((void**)&h2, g_h2);
    cudaGetSymbolAddress((void**)&f1, g_f1);

    const dim3 blk(256);
    const dim3 gD(Dz / 128, Mz / 128);    // (8, 64)
    const dim3 gF(DFFz / 128, Mz / 128);  // (32, 64)

    // LN1
    ln_kernel<<<Mz, 256>>>(x, g1, be1, h1);
    // QKV projections
    sgemm_kernel<false, false, false><<<gD, blk>>>(h1, wq, nullptr, nullptr, q,  Mz, Dz, Dz);
    sgemm_kernel<false, false, false><<<gD, blk>>>(h1, wk, nullptr, nullptr, k,  Mz, Dz, Dz);
    sgemm_kernel<false, false, false><<<gD, blk>>>(h1, wv, nullptr, nullptr, v,  Mz, Dz, Dz);
    // causal attention
    attn_kernel<<<dim3(Sz / 64, Bz * Hz), 64>>>(q, k, v, at);
    // output projection + bias + residual
    sgemm_kernel<false, true, true><<<gD, blk>>>(at, wo, bo, x, x2, Mz, Dz, Dz);
    // LN2
    ln_kernel<<<Mz, 256>>>(x2, g2, be2, h2);
    // FF1 with exact GELU
    sgemm_kernel<true, true, false><<<gF, blk>>>(h2, w1, b1, nullptr, f1, Mz, DFFz, Dz);
    // FF2 + bias + residual -> final output
    sgemm_kernel<false, true, true><<<gD, blk>>>(f1, w2, b2, x2, out, Mz, Dz, DFFz);
}

// round 3
// speedup vs baseline: 1.6990x; 1.6990x over previous
#include <cuda_runtime.h>
#include <cuda_bf16.h>
#include <math.h>
#include <stddef.h>
#include <stdint.h>

// Problem dimensions (fixed by the reference)
#define Bz   4
#define Sz   2048
#define Dz   1024
#define Hz   16
#define DKz  64
#define DFFz 4096
#define Mz   (Bz * Sz)   // 8192 rows

// ---------------------------------------------------------------------------
// Scratch buffers (device globals: no allocation allowed in kernel_launch)
// bf16x3 split GEMM along K:
//   A expanded [M, 3K] = [Ah | Ah | Al]
//   B expanded [3K, N] = [Bh ; Bl ; Bh]
//   plain bf16 GEMM with K' = 3K computes Ah*Bh + Ah*Bl + Al*Bh ~= fp32 GEMM.
// ---------------------------------------------------------------------------
static __device__ __nv_bfloat16 g_h1x[(size_t)Mz * 3 * Dz];    // LN1 out, expanded
static __device__ float         g_q [(size_t)Mz * Dz];
static __device__ float         g_k [(size_t)Mz * Dz];
static __device__ float         g_v [(size_t)Mz * Dz];
static __device__ __nv_bfloat16 g_atx[(size_t)Mz * 3 * Dz];    // attn out, expanded
static __device__ float         g_x2[(size_t)Mz * Dz];         // residual-1
static __device__ __nv_bfloat16 g_h2x[(size_t)Mz * 3 * Dz];    // LN2 out, expanded
static __device__ __nv_bfloat16 g_f1x[(size_t)Mz * 3 * DFFz];  // gelu(ff1), expanded
// expanded weights [3K, N]
static __device__ __nv_bfloat16 g_wqx[(size_t)3 * Dz * Dz];
static __device__ __nv_bfloat16 g_wkx[(size_t)3 * Dz * Dz];
static __device__ __nv_bfloat16 g_wvx[(size_t)3 * Dz * Dz];
static __device__ __nv_bfloat16 g_wox[(size_t)3 * Dz * Dz];
static __device__ __nv_bfloat16 g_w1x[(size_t)3 * Dz * DFFz];
static __device__ __nv_bfloat16 g_w2x[(size_t)3 * DFFz * Dz];

// ---------------------------------------------------------------------------
// helpers
// ---------------------------------------------------------------------------
__device__ __forceinline__ float gelu_exact(float x)
{
    return 0.5f * x * (1.0f + erff(x * 0.70710678118654752440f));
}

__device__ __forceinline__ void split2(float y0, float y1,
                                       __nv_bfloat162& hh, __nv_bfloat162& ll)
{
    __nv_bfloat16 h0 = __float2bfloat16(y0);
    __nv_bfloat16 h1 = __float2bfloat16(y1);
    __nv_bfloat16 l0 = __float2bfloat16(y0 - __bfloat162float(h0));
    __nv_bfloat16 l1 = __float2bfloat16(y1 - __bfloat162float(h1));
    hh = __halves2bfloat162(h0, h1);
    ll = __halves2bfloat162(l0, l1);
}

__device__ __forceinline__ void ldsm_x4(unsigned* r, uint32_t addr)
{
    asm volatile("ldmatrix.sync.aligned.m8n8.x4.shared.b16 {%0,%1,%2,%3}, [%4];\n"
                 : "=r"(r[0]), "=r"(r[1]), "=r"(r[2]), "=r"(r[3]) : "r"(addr));
}
__device__ __forceinline__ void ldsm_x4_t(unsigned* r, uint32_t addr)
{
    asm volatile("ldmatrix.sync.aligned.m8n8.x4.trans.shared.b16 {%0,%1,%2,%3}, [%4];\n"
                 : "=r"(r[0]), "=r"(r[1]), "=r"(r[2]), "=r"(r[3]) : "r"(addr));
}
__device__ __forceinline__ void mma_bf16(float* d, const unsigned* a,
                                         const unsigned* b, const float* c)
{
    asm volatile(
        "mma.sync.aligned.m16n8k16.row.col.f32.bf16.bf16.f32 "
        "{%0,%1,%2,%3}, {%4,%5,%6,%7}, {%8,%9}, {%10,%11,%12,%13};\n"
        : "=f"(d[0]), "=f"(d[1]), "=f"(d[2]), "=f"(d[3])
        : "r"(a[0]), "r"(a[1]), "r"(a[2]), "r"(a[3]), "r"(b[0]), "r"(b[1]),
          "f"(c[0]), "f"(c[1]), "f"(c[2]), "f"(c[3]));
}
__device__ __forceinline__ void cp_async16(uint32_t dst, const void* src)
{
    asm volatile("cp.async.cg.shared.global [%0], [%1], 16;\n"
                 :: "r"(dst), "l"(src) : "memory");
}
__device__ __forceinline__ void cp_commit()
{
    asm volatile("cp.async.commit_group;\n" ::: "memory");
}
__device__ __forceinline__ void cp_wait1()
{
    asm volatile("cp.async.wait_group 1;\n" ::: "memory");
}
__device__ __forceinline__ void cp_wait0()
{
    asm volatile("cp.async.wait_group 0;\n" ::: "memory");
}

// ---------------------------------------------------------------------------
// Weight expansion: W[K,N] fp32 -> Wx[3K,N] bf16, segments [hi ; lo ; hi]
// (pairs with activation segments [hi | hi | lo])
// ---------------------------------------------------------------------------
__global__ __launch_bounds__(256)
void wexpand_kernel(const float* __restrict__ W, __nv_bfloat16* __restrict__ Wx,
                    int K, int N)
{
    size_t idx = (size_t)blockIdx.x * blockDim.x + threadIdx.x;
    size_t total = ((size_t)K * N) >> 2;
    if (idx >= total) return;
    size_t e = idx << 2;
    int k = (int)(e / N);
    int n = (int)(e % N);
    float4 w = *(const float4*)(W + e);
    __nv_bfloat162 hh0, ll0, hh1, ll1;
    split2(w.x, w.y, hh0, ll0);
    split2(w.z, w.w, hh1, ll1);
    size_t b0 = (size_t)k * N + n;                 // segment 0: hi
    size_t b1 = ((size_t)K + k) * N + n;           // segment 1: lo
    size_t b2 = ((size_t)2 * K + k) * N + n;       // segment 2: hi
    *(__nv_bfloat162*)(Wx + b0)     = hh0;
    *(__nv_bfloat162*)(Wx + b0 + 2) = hh1;
    *(__nv_bfloat162*)(Wx + b1)     = ll0;
    *(__nv_bfloat162*)(Wx + b1 + 2) = ll1;
    *(__nv_bfloat162*)(Wx + b2)     = hh0;
    *(__nv_bfloat162*)(Wx + b2 + 2) = hh1;
}

// ---------------------------------------------------------------------------
// LayerNorm + expand: one block per row of 1024, 256 threads, float4/thread.
// Output: bf16 expanded [row][3*D] = [hi | hi | lo]
// ---------------------------------------------------------------------------
__global__ __launch_bounds__(256)
void ln_expand_kernel(const float* __restrict__ x, const float* __restrict__ g,
                      const float* __restrict__ bt, __nv_bfloat16* __restrict__ out)
{
    const int row = blockIdx.x;
    const int tid = threadIdx.x;
    const float4* xr = (const float4*)(x + (size_t)row * Dz);
    float4 v = xr[tid];

    float s  = v.x + v.y + v.z + v.w;
    float s2 = v.x * v.x + v.y * v.y + v.z * v.z + v.w * v.w;
    #pragma unroll
    for (int o = 16; o > 0; o >>= 1) {
        s  += __shfl_xor_sync(0xffffffffu, s,  o);
        s2 += __shfl_xor_sync(0xffffffffu, s2, o);
    }
    __shared__ float ws[8], ws2[8];
    const int wid = tid >> 5, lane = tid & 31;
    if (lane == 0) { ws[wid] = s; ws2[wid] = s2; }
    __syncthreads();
    __shared__ float s_mean, s_inv;
    if (tid == 0) {
        float a = 0.f, b = 0.f;
        #pragma unroll
        for (int i = 0; i < 8; i++) { a += ws[i]; b += ws2[i]; }
        float mean = a * (1.0f / Dz);
        float var  = b * (1.0f / Dz) - mean * mean;
        s_mean = mean;
        s_inv  = rsqrtf(var + 1e-5f);
    }
    __syncthreads();
    const float mean = s_mean, inv = s_inv;

    float4 gg = ((const float4*)g)[tid];
    float4 bb = ((const float4*)bt)[tid];
    float y0 = (v.x - mean) * inv * gg.x + bb.x;
    float y1 = (v.y - mean) * inv * gg.y + bb.y;
    float y2 = (v.z - mean) * inv * gg.z + bb.z;
    float y3 = (v.w - mean) * inv * gg.w + bb.w;

    __nv_bfloat162 hh0, ll0, hh1, ll1;
    split2(y0, y1, hh0, ll0);
    split2(y2, y3, hh1, ll1);
    const int col = tid * 4;
    __nv_bfloat16* o = out + (size_t)row * (3 * Dz) + col;
    *(__nv_bfloat162*)(o)              = hh0;
    *(__nv_bfloat162*)(o + 2)          = hh1;
    *(__nv_bfloat162*)(o + Dz)         = hh0;
    *(__nv_bfloat162*)(o + Dz + 2)     = hh1;
    *(__nv_bfloat162*)(o + 2 * Dz)     = ll0;
    *(__nv_bfloat162*)(o + 2 * Dz + 2) = ll1;
}

// ---------------------------------------------------------------------------
// bf16 tensor-core GEMM: C[M,N] = A[M,Kp] @ B[Kp,N]
// Block 128x128, BK=32, 256 threads (8 warps, 4x2), warp tile 32x64.
// cp.async double-buffered, ldmatrix with XOR-swizzled smem.
// OUTMODE 0: fp32 C (+bias)(+gelu)(+res)
// OUTMODE 1: expanded bf16 C [M, 3N] (+bias)(+gelu)
// ---------------------------------------------------------------------------
template<int OUTMODE, bool GELU, bool BIAS, bool RES>
__global__ __launch_bounds__(256, 2)
void gemm_bf16(const __nv_bfloat16* __restrict__ A, const __nv_bfloat16* __restrict__ B,
               const float* __restrict__ bias, const float* __restrict__ res,
               void* __restrict__ Cout, int Mi, int Ni, int Kp)
{
    __shared__ __align__(128) __nv_bfloat16 shA[2][128 * 32]; // 8KB each
    __shared__ __align__(128) __nv_bfloat16 shB[2][32 * 128]; // 8KB each

    const int tid = threadIdx.x;
    const int lane = tid & 31;
    const int wid = tid >> 5;
    const int warp_m = wid & 3;   // 4 warps along M (32 rows each)
    const int warp_n = wid >> 2;  // 2 warps along N (64 cols each)
    const int bm = blockIdx.y * 128;
    const int bn = blockIdx.x * 128;

    const uint32_t saBase = (uint32_t)__cvta_generic_to_shared(&shA[0][0]);
    const uint32_t sbBase = (uint32_t)__cvta_generic_to_shared(&shB[0][0]);

    float acc[2][8][4];
    #pragma unroll
    for (int mt = 0; mt < 2; mt++)
        #pragma unroll
        for (int nt = 0; nt < 8; nt++)
            #pragma unroll
            for (int i = 0; i < 4; i++) acc[mt][nt][i] = 0.f;

    auto load_tile = [&](int buf, int kt) {
        #pragma unroll
        for (int i = 0; i < 2; i++) {
            int idx = i * 256 + tid;
            int m = idx >> 2, c = idx & 3;
            const void* src = A + (size_t)(bm + m) * Kp + kt * 32 + c * 8;
            uint32_t dst = saBase + buf * 8192 + (m << 6) + ((c ^ ((m >> 1) & 3)) << 4);
            cp_async16(dst, src);
        }
        #pragma unroll
        for (int i = 0; i < 2; i++) {
            int idx = i * 256 + tid;
            int k = idx >> 4, c = idx & 15;
            const void* src = B + (size_t)(kt * 32 + k) * Ni + bn + c * 8;
            uint32_t dst = sbBase + buf * 8192 + (k << 8) + ((c ^ (k & 7)) << 4);
            cp_async16(dst, src);
        }
    };

    const int l7  = lane & 7;
    const int l8  = (lane >> 3) & 1;
    const int l16 = lane >> 4;

    auto compute = [&](int buf) {
        uint32_t sa = saBase + buf * 8192;
        uint32_t sb = sbBase + buf * 8192;
        #pragma unroll
        for (int ks = 0; ks < 2; ks++) {
            unsigned ra[2][4], rb[4][4];
            #pragma unroll
            for (int mt = 0; mt < 2; mt++) {
                int row = warp_m * 32 + mt * 16 + l7 + l8 * 8;
                int c   = ks * 2 + l16;
                ldsm_x4(ra[mt], sa + (row << 6) + ((c ^ ((row >> 1) & 3)) << 4));
            }
            #pragma unroll
            for (int p = 0; p < 4; p++) {
                int k = ks * 16 + l7 + l8 * 8;
                int c = warp_n * 8 + p * 2 + l16;
                ldsm_x4_t(rb[p], sb + (k << 8) + ((c ^ (k & 7)) << 4));
            }
            #pragma unroll
            for (int mt = 0; mt < 2; mt++)
                #pragma unroll
                for (int nt = 0; nt < 8; nt++)
                    mma_bf16(acc[mt][nt], ra[mt], &rb[nt >> 1][(nt & 1) * 2], acc[mt][nt]);
        }
    };

    const int NK = Kp / 32;
    load_tile(0, 0);
    cp_commit();
    for (int kt = 0; kt < NK; kt++) {
        int buf = kt & 1;
        if (kt + 1 < NK) { load_tile(buf ^ 1, kt + 1); cp_commit(); cp_wait1(); }
        else            { cp_wait0(); }
        __syncthreads();
        compute(buf);
        __syncthreads();
    }

    // epilogue
    const int g = lane >> 2, t = lane & 3;
    #pragma unroll
    for (int mt = 0; mt < 2; mt++) {
        #pragma unroll
        for (int nt = 0; nt < 8; nt++) {
            const int col = bn + warp_n * 64 + nt * 8 + 2 * t;
            #pragma unroll
            for (int half = 0; half < 2; half++) {
                const int r = bm + warp_m * 32 + mt * 16 + g + half * 8;
                float v0 = acc[mt][nt][half * 2 + 0];
                float v1 = acc[mt][nt][half * 2 + 1];
                if (BIAS) { v0 += bias[col]; v1 += bias[col + 1]; }
                if (GELU) { v0 = gelu_exact(v0); v1 = gelu_exact(v1); }
                if (RES) {
                    const float* rp = res + (size_t)r * Ni + col;
                    v0 += rp[0]; v1 += rp[1];
                }
                if (OUTMODE == 0) {
                    float2 o; o.x = v0; o.y = v1;
                    *(float2*)((float*)Cout + (size_t)r * Ni + col) = o;
                } else {
                    __nv_bfloat162 hh, ll;
                    split2(v0, v1, hh, ll);
                    __nv_bfloat16* Cb = (__nv_bfloat16*)Cout;
                    size_t base = (size_t)r * (3 * Ni) + col;
                    *(__nv_bfloat162*)(Cb + base)          = hh;
                    *(__nv_bfloat162*)(Cb + base + Ni)     = hh;
                    *(__nv_bfloat162*)(Cb + base + 2 * Ni) = ll;
                }
            }
        }
    }
}

// ---------------------------------------------------------------------------
// Causal flash attention, fp32, writes expanded bf16 output for the WO GEMM.
// ---------------------------------------------------------------------------
__global__ __launch_bounds__(64)
void attn_kernel(const float* __restrict__ Q, const float* __restrict__ K,
                 const float* __restrict__ V, __nv_bfloat16* __restrict__ O)
{
    const int qt  = blockIdx.x;
    const int bh  = blockIdx.y;
    const int b   = bh / Hz;
    const int h   = bh % Hz;
    const int tid = threadIdx.x;
    const int sq  = qt * 64 + tid;

    __shared__ __align__(16) float4 Ks[64][16];
    __shared__ __align__(16) float4 Vs[64][16];

    float qr[64];
    {
        const float4* qrow =
            (const float4*)(Q + ((size_t)(b * Sz + sq)) * Dz + h * DKz);
        const float scale = 0.125f;
        #pragma unroll
        for (int i = 0; i < 16; i++) {
            float4 tq = qrow[i];
            qr[4 * i + 0] = tq.x * scale; qr[4 * i + 1] = tq.y * scale;
            qr[4 * i + 2] = tq.z * scale; qr[4 * i + 3] = tq.w * scale;
        }
    }

    float out[64];
    #pragma unroll
    for (int i = 0; i < 64; i++) out[i] = 0.f;
    float m = -INFINITY, l = 0.f;

    for (int kt = 0; kt <= qt; kt++) {
        #pragma unroll
        for (int it = 0; it < 16; it++) {
            const int idx = it * 64 + tid;
            const int j = idx >> 4, c = idx & 15;
            const size_t gofs =
                ((size_t)(b * Sz + kt * 64 + j)) * Dz + h * DKz + c * 4;
            Ks[j][c] = *(const float4*)(K + gofs);
            Vs[j][c] = *(const float4*)(V + gofs);
        }
        __syncthreads();

        const bool diag = (kt == qt);

        #pragma unroll 1
        for (int j0 = 0; j0 < 64; j0 += 8) {
            float s[8];
            #pragma unroll
            for (int jj = 0; jj < 8; jj++) {
                const float4* kr = Ks[j0 + jj];
                float ax = 0.f, ay = 0.f, az = 0.f, aw = 0.f;
                #pragma unroll
                for (int c = 0; c < 16; c++) {
                    float4 kv = kr[c];
                    ax = fmaf(qr[4 * c + 0], kv.x, ax);
                    ay = fmaf(qr[4 * c + 1], kv.y, ay);
                    az = fmaf(qr[4 * c + 2], kv.z, az);
                    aw = fmaf(qr[4 * c + 3], kv.w, aw);
                }
                s[jj] = (ax + ay) + (az + aw);
                if (diag && (j0 + jj) > tid) s[jj] = -INFINITY;
            }
            float mt = m;
            #pragma unroll
            for (int jj = 0; jj < 8; jj++) mt = fmaxf(mt, s[jj]);
            const float corr = __expf(m - mt);
            m = mt;
            l *= corr;
            #pragma unroll
            for (int dd = 0; dd < 64; dd++) out[dd] *= corr;
            #pragma unroll
            for (int jj = 0; jj < 8; jj++) {
                const float p = __expf(s[jj] - m);
                l += p;
                const float4* vr = Vs[j0 + jj];
                #pragma unroll
                for (int c = 0; c < 16; c++) {
                    float4 vv = vr[c];
                    out[4 * c + 0] = fmaf(p, vv.x, out[4 * c + 0]);
                    out[4 * c + 1] = fmaf(p, vv.y, out[4 * c + 1]);
                    out[4 * c + 2] = fmaf(p, vv.z, out[4 * c + 2]);
                    out[4 * c + 3] = fmaf(p, vv.w, out[4 * c + 3]);
                }
            }
        }
        __syncthreads();
    }

    const float inv = 1.0f / l;
    const size_t base = ((size_t)(b * Sz + sq)) * (3 * Dz) + h * DKz;
    #pragma unroll
    for (int i = 0; i < 32; i++) {
        float y0 = out[2 * i + 0] * inv;
        float y1 = out[2 * i + 1] * inv;
        __nv_bfloat162 hh, ll;
        split2(y0, y1, hh, ll);
        *(__nv_bfloat162*)(O + base + 2 * i)          = hh;
        *(__nv_bfloat162*)(O + base + Dz + 2 * i)     = hh;
        *(__nv_bfloat162*)(O + base + 2 * Dz + 2 * i) = ll;
    }
}

// ---------------------------------------------------------------------------
// Launcher
// ---------------------------------------------------------------------------
extern "C" void kernel_launch(void* const* d_in, const int* in_sizes, int n_in,
                              void* d_out, int out_size)
{
    (void)in_sizes; (void)n_in; (void)out_size;

    const float* x   = (const float*)d_in[0];
    const float* wq  = (const float*)d_in[1];
    const float* wk  = (const float*)d_in[2];
    const float* wv  = (const float*)d_in[3];
    const float* wo  = (const float*)d_in[4];
    const float* bo  = (const float*)d_in[5];
    const float* w1  = (const float*)d_in[6];
    const float* b1  = (const float*)d_in[7];
    const float* w2  = (const float*)d_in[8];
    const float* b2  = (const float*)d_in[9];
    const float* g1  = (const float*)d_in[10];
    const float* be1 = (const float*)d_in[11];
    const float* g2  = (const float*)d_in[12];
    const float* be2 = (const float*)d_in[13];
    float* out = (float*)d_out;

    __nv_bfloat16 *h1x, *atx, *h2x, *f1x, *wqx, *wkx, *wvx, *wox, *w1x, *w2x;
    float *q, *k, *v, *x2;
    cudaGetSymbolAddress((void**)&h1x, g_h1x);
    cudaGetSymbolAddress((void**)&q,   g_q);
    cudaGetSymbolAddress((void**)&k,   g_k);
    cudaGetSymbolAddress((void**)&v,   g_v);
    cudaGetSymbolAddress((void**)&atx, g_atx);
    cudaGetSymbolAddress((void**)&x2,  g_x2);
    cudaGetSymbolAddress((void**)&h2x, g_h2x);
    cudaGetSymbolAddress((void**)&f1x, g_f1x);
    cudaGetSymbolAddress((void**)&wqx, g_wqx);
    cudaGetSymbolAddress((void**)&wkx, g_wkx);
    cudaGetSymbolAddress((void**)&wvx, g_wvx);
    cudaGetSymbolAddress((void**)&wox, g_wox);
    cudaGetSymbolAddress((void**)&w1x, g_w1x);
    cudaGetSymbolAddress((void**)&w2x, g_w2x);

    // expand weights to bf16x3
    {
        int nDD  = (Dz * Dz) / 4;          // 262144 elems of float4
        int nDF  = (Dz * DFFz) / 4;
        wexpand_kernel<<<(nDD + 255) / 256, 256>>>(wq, wqx, Dz, Dz);
        wexpand_kernel<<<(nDD + 255) / 256, 256>>>(wk, wkx, Dz, Dz);
        wexpand_kernel<<<(nDD + 255) / 256, 256>>>(wv, wvx, Dz, Dz);
        wexpand_kernel<<<(nDD + 255) / 256, 256>>>(wo, wox, Dz, Dz);
        wexpand_kernel<<<(nDF + 255) / 256, 256>>>(w1, w1x, Dz, DFFz);
        wexpand_kernel<<<(nDF + 255) / 256, 256>>>(w2, w2x, DFFz, Dz);
    }

    const dim3 blk(256);
    const dim3 gD(Dz / 128, Mz / 128);    // (8, 64)
    const dim3 gF(DFFz / 128, Mz / 128);  // (32, 64)
    const int KD = 3 * Dz;    // 3072
    const int KF = 3 * DFFz;  // 12288

    // LN1 (expanded)
    ln_expand_kernel<<<Mz, 256>>>(x, g1, be1, h1x);
    // QKV projections (fp32 out)
    gemm_bf16<0, false, false, false><<<gD, blk>>>(h1x, wqx, nullptr, nullptr, q, Mz, Dz, KD);
    gemm_bf16<0, false, false, false><<<gD, blk>>>(h1x, wkx, nullptr, nullptr, k, Mz, Dz, KD);
    gemm_bf16<0, false, false, false><<<gD, blk>>>(h1x, wvx, nullptr, nullptr, v, Mz, Dz, KD);
    // causal attention -> expanded bf16
    attn_kernel<<<dim3(Sz / 64, Bz * Hz), 64>>>(q, k, v, atx);
    // output projection + bias + residual(x) -> x2 (fp32)
    gemm_bf16<0, false, true, true><<<gD, blk>>>(atx, wox, bo, x, x2, Mz, Dz, KD);
    // LN2 (expanded)
    ln_expand_kernel<<<Mz, 256>>>(x2, g2, be2, h2x);
    // FF1 + bias + exact GELU -> expanded bf16
    gemm_bf16<1, true, true, false><<<gF, blk>>>(h2x, w1x, b1, nullptr, f1x, Mz, DFFz, KD);
    // FF2 + bias + residual(x2) -> final output (fp32)
    gemm_bf16<0, false, true, true><<<gD, blk>>>(f1x, w2x, b2, x2, out, Mz, Dz, KF);
}

// round 4
// speedup vs baseline: 2.6497x; 1.5595x over previous
#include <cuda_runtime.h>
#include <cuda_bf16.h>
#include <math.h>
#include <stddef.h>
#include <stdint.h>

// Problem dimensions (fixed by the reference)
#define Bz   4
#define Sz   2048
#define Dz   1024
#define Hz   16
#define DKz  64
#define DFFz 4096
#define Mz   (Bz * Sz)   // 8192 rows

// ---------------------------------------------------------------------------
// Scratch buffers (device globals)
// bf16x3 split GEMM along K:
//   A expanded [M, 3K] = [Ah | Ah | Al]
//   B expanded [3K, N] = [Bh ; Bl ; Bh]
// ---------------------------------------------------------------------------
static __device__ __nv_bfloat16 g_h1x[(size_t)Mz * 3 * Dz];    // LN1 out, expanded
static __device__ float         g_q [(size_t)Mz * Dz];
static __device__ float         g_k [(size_t)Mz * Dz];
static __device__ float         g_v [(size_t)Mz * Dz];
static __device__ __nv_bfloat16 g_atx[(size_t)Mz * 3 * Dz];    // attn out, expanded
static __device__ float         g_x2[(size_t)Mz * Dz];         // residual-1
static __device__ __nv_bfloat16 g_h2x[(size_t)Mz * 3 * Dz];    // LN2 out, expanded
static __device__ __nv_bfloat16 g_f1x[(size_t)Mz * 3 * DFFz];  // gelu(ff1), expanded
static __device__ __nv_bfloat16 g_wqx[(size_t)3 * Dz * Dz];
static __device__ __nv_bfloat16 g_wkx[(size_t)3 * Dz * Dz];
static __device__ __nv_bfloat16 g_wvx[(size_t)3 * Dz * Dz];
static __device__ __nv_bfloat16 g_wox[(size_t)3 * Dz * Dz];
static __device__ __nv_bfloat16 g_w1x[(size_t)3 * Dz * DFFz];
static __device__ __nv_bfloat16 g_w2x[(size_t)3 * DFFz * Dz];

// ---------------------------------------------------------------------------
// helpers
// ---------------------------------------------------------------------------
__device__ __forceinline__ float gelu_exact(float x)
{
    return 0.5f * x * (1.0f + erff(x * 0.70710678118654752440f));
}

__device__ __forceinline__ void split2(float y0, float y1,
                                       __nv_bfloat162& hh, __nv_bfloat162& ll)
{
    __nv_bfloat16 h0 = __float2bfloat16(y0);
    __nv_bfloat16 h1 = __float2bfloat16(y1);
    __nv_bfloat16 l0 = __float2bfloat16(y0 - __bfloat162float(h0));
    __nv_bfloat16 l1 = __float2bfloat16(y1 - __bfloat162float(h1));
    hh = __halves2bfloat162(h0, h1);
    ll = __halves2bfloat162(l0, l1);
}

__device__ __forceinline__ unsigned pack_bf2(float a, float b)
{
    __nv_bfloat162 t = __halves2bfloat162(__float2bfloat16(a), __float2bfloat16(b));
    return *(unsigned*)&t;
}
// split a pair into packed hi and packed lo
__device__ __forceinline__ void split_pack(float a, float b, unsigned& hi, unsigned& lo)
{
    __nv_bfloat16 ha = __float2bfloat16(a);
    __nv_bfloat16 hb = __float2bfloat16(b);
    float ra = a - __bfloat162float(ha);
    float rb = b - __bfloat162float(hb);
    __nv_bfloat162 th = __halves2bfloat162(ha, hb);
    __nv_bfloat162 tl = __halves2bfloat162(__float2bfloat16(ra), __float2bfloat16(rb));
    hi = *(unsigned*)&th;
    lo = *(unsigned*)&tl;
}

__device__ __forceinline__ void ldsm_x4(unsigned* r, uint32_t addr)
{
    asm volatile("ldmatrix.sync.aligned.m8n8.x4.shared.b16 {%0,%1,%2,%3}, [%4];\n"
                 : "=r"(r[0]), "=r"(r[1]), "=r"(r[2]), "=r"(r[3]) : "r"(addr));
}
__device__ __forceinline__ void ldsm_x4_t(unsigned* r, uint32_t addr)
{
    asm volatile("ldmatrix.sync.aligned.m8n8.x4.trans.shared.b16 {%0,%1,%2,%3}, [%4];\n"
                 : "=r"(r[0]), "=r"(r[1]), "=r"(r[2]), "=r"(r[3]) : "r"(addr));
}
__device__ __forceinline__ void mma_bf16(float* d, const unsigned* a,
                                         const unsigned* b, const float* c)
{
    asm volatile(
        "mma.sync.aligned.m16n8k16.row.col.f32.bf16.bf16.f32 "
        "{%0,%1,%2,%3}, {%4,%5,%6,%7}, {%8,%9}, {%10,%11,%12,%13};\n"
        : "=f"(d[0]), "=f"(d[1]), "=f"(d[2]), "=f"(d[3])
        : "r"(a[0]), "r"(a[1]), "r"(a[2]), "r"(a[3]), "r"(b[0]), "r"(b[1]),
          "f"(c[0]), "f"(c[1]), "f"(c[2]), "f"(c[3]));
}
__device__ __forceinline__ void cp_async16(uint32_t dst, const void* src)
{
    asm volatile("cp.async.cg.shared.global [%0], [%1], 16;\n"
                 :: "r"(dst), "l"(src) : "memory");
}
__device__ __forceinline__ void cp_commit()
{
    asm volatile("cp.async.commit_group;\n" ::: "memory");
}
__device__ __forceinline__ void cp_wait1()
{
    asm volatile("cp.async.wait_group 1;\n" ::: "memory");
}
__device__ __forceinline__ void cp_wait0()
{
    asm volatile("cp.async.wait_group 0;\n" ::: "memory");
}

// ---------------------------------------------------------------------------
// Weight expansion: W[K,N] fp32 -> Wx[3K,N] bf16, segments [hi ; lo ; hi]
// ---------------------------------------------------------------------------
__global__ __launch_bounds__(256)
void wexpand_kernel(const float* __restrict__ W, __nv_bfloat16* __restrict__ Wx,
                    int K, int N)
{
    size_t idx = (size_t)blockIdx.x * blockDim.x + threadIdx.x;
    size_t total = ((size_t)K * N) >> 2;
    if (idx >= total) return;
    size_t e = idx << 2;
    int k = (int)(e / N);
    int n = (int)(e % N);
    float4 w = *(const float4*)(W + e);
    __nv_bfloat162 hh0, ll0, hh1, ll1;
    split2(w.x, w.y, hh0, ll0);
    split2(w.z, w.w, hh1, ll1);
    size_t b0 = (size_t)k * N + n;                 // segment 0: hi
    size_t b1 = ((size_t)K + k) * N + n;           // segment 1: lo
    size_t b2 = ((size_t)2 * K + k) * N + n;       // segment 2: hi
    *(__nv_bfloat162*)(Wx + b0)     = hh0;
    *(__nv_bfloat162*)(Wx + b0 + 2) = hh1;
    *(__nv_bfloat162*)(Wx + b1)     = ll0;
    *(__nv_bfloat162*)(Wx + b1 + 2) = ll1;
    *(__nv_bfloat162*)(Wx + b2)     = hh0;
    *(__nv_bfloat162*)(Wx + b2 + 2) = hh1;
}

// ---------------------------------------------------------------------------
// LayerNorm + expand
// ---------------------------------------------------------------------------
__global__ __launch_bounds__(256)
void ln_expand_kernel(const float* __restrict__ x, const float* __restrict__ g,
                      const float* __restrict__ bt, __nv_bfloat16* __restrict__ out)
{
    const int row = blockIdx.x;
    const int tid = threadIdx.x;
    const float4* xr = (const float4*)(x + (size_t)row * Dz);
    float4 v = xr[tid];

    float s  = v.x + v.y + v.z + v.w;
    float s2 = v.x * v.x + v.y * v.y + v.z * v.z + v.w * v.w;
    #pragma unroll
    for (int o = 16; o > 0; o >>= 1) {
        s  += __shfl_xor_sync(0xffffffffu, s,  o);
        s2 += __shfl_xor_sync(0xffffffffu, s2, o);
    }
    __shared__ float ws[8], ws2[8];
    const int wid = tid >> 5, lane = tid & 31;
    if (lane == 0) { ws[wid] = s; ws2[wid] = s2; }
    __syncthreads();
    __shared__ float s_mean, s_inv;
    if (tid == 0) {
        float a = 0.f, b = 0.f;
        #pragma unroll
        for (int i = 0; i < 8; i++) { a += ws[i]; b += ws2[i]; }
        float mean = a * (1.0f / Dz);
        float var  = b * (1.0f / Dz) - mean * mean;
        s_mean = mean;
        s_inv  = rsqrtf(var + 1e-5f);
    }
    __syncthreads();
    const float mean = s_mean, inv = s_inv;

    float4 gg = ((const float4*)g)[tid];
    float4 bb = ((const float4*)bt)[tid];
    float y0 = (v.x - mean) * inv * gg.x + bb.x;
    float y1 = (v.y - mean) * inv * gg.y + bb.y;
    float y2 = (v.z - mean) * inv * gg.z + bb.z;
    float y3 = (v.w - mean) * inv * gg.w + bb.w;

    __nv_bfloat162 hh0, ll0, hh1, ll1;
    split2(y0, y1, hh0, ll0);
    split2(y2, y3, hh1, ll1);
    const int col = tid * 4;
    __nv_bfloat16* o = out + (size_t)row * (3 * Dz) + col;
    *(__nv_bfloat162*)(o)              = hh0;
    *(__nv_bfloat162*)(o + 2)          = hh1;
    *(__nv_bfloat162*)(o + Dz)         = hh0;
    *(__nv_bfloat162*)(o + Dz + 2)     = hh1;
    *(__nv_bfloat162*)(o + 2 * Dz)     = ll0;
    *(__nv_bfloat162*)(o + 2 * Dz + 2) = ll1;
}

// ---------------------------------------------------------------------------
// bf16 tensor-core GEMM (unchanged from R2, passing)
// ---------------------------------------------------------------------------
template<int OUTMODE, bool GELU, bool BIAS, bool RES>
__global__ __launch_bounds__(256, 2)
void gemm_bf16(const __nv_bfloat16* __restrict__ A, const __nv_bfloat16* __restrict__ B,
               const float* __restrict__ bias, const float* __restrict__ res,
               void* __restrict__ Cout, int Mi, int Ni, int Kp)
{
    __shared__ __align__(128) __nv_bfloat16 shA[2][128 * 32];
    __shared__ __align__(128) __nv_bfloat16 shB[2][32 * 128];

    const int tid = threadIdx.x;
    const int lane = tid & 31;
    const int wid = tid >> 5;
    const int warp_m = wid & 3;
    const int warp_n = wid >> 2;
    const int bm = blockIdx.y * 128;
    const int bn = blockIdx.x * 128;

    const uint32_t saBase = (uint32_t)__cvta_generic_to_shared(&shA[0][0]);
    const uint32_t sbBase = (uint32_t)__cvta_generic_to_shared(&shB[0][0]);

    float acc[2][8][4];
    #pragma unroll
    for (int mt = 0; mt < 2; mt++)
        #pragma unroll
        for (int nt = 0; nt < 8; nt++)
            #pragma unroll
            for (int i = 0; i < 4; i++) acc[mt][nt][i] = 0.f;

    auto load_tile = [&](int buf, int kt) {
        #pragma unroll
        for (int i = 0; i < 2; i++) {
            int idx = i * 256 + tid;
            int m = idx >> 2, c = idx & 3;
            const void* src = A + (size_t)(bm + m) * Kp + kt * 32 + c * 8;
            uint32_t dst = saBase + buf * 8192 + (m << 6) + ((c ^ ((m >> 1) & 3)) << 4);
            cp_async16(dst, src);
        }
        #pragma unroll
        for (int i = 0; i < 2; i++) {
            int idx = i * 256 + tid;
            int k = idx >> 4, c = idx & 15;
            const void* src = B + (size_t)(kt * 32 + k) * Ni + bn + c * 8;
            uint32_t dst = sbBase + buf * 8192 + (k << 8) + ((c ^ (k & 7)) << 4);
            cp_async16(dst, src);
        }
    };

    const int l7  = lane & 7;
    const int l8  = (lane >> 3) & 1;
    const int l16 = lane >> 4;

    auto compute = [&](int buf) {
        uint32_t sa = saBase + buf * 8192;
        uint32_t sb = sbBase + buf * 8192;
        #pragma unroll
        for (int ks = 0; ks < 2; ks++) {
            unsigned ra[2][4], rb[4][4];
            #pragma unroll
            for (int mt = 0; mt < 2; mt++) {
                int row = warp_m * 32 + mt * 16 + l7 + l8 * 8;
                int c   = ks * 2 + l16;
                ldsm_x4(ra[mt], sa + (row << 6) + ((c ^ ((row >> 1) & 3)) << 4));
            }
            #pragma unroll
            for (int p = 0; p < 4; p++) {
                int k = ks * 16 + l7 + l8 * 8;
                int c = warp_n * 8 + p * 2 + l16;
                ldsm_x4_t(rb[p], sb + (k << 8) + ((c ^ (k & 7)) << 4));
            }
            #pragma unroll
            for (int mt = 0; mt < 2; mt++)
                #pragma unroll
                for (int nt = 0; nt < 8; nt++)
                    mma_bf16(acc[mt][nt], ra[mt], &rb[nt >> 1][(nt & 1) * 2], acc[mt][nt]);
        }
    };

    const int NK = Kp / 32;
    load_tile(0, 0);
    cp_commit();
    for (int kt = 0; kt < NK; kt++) {
        int buf = kt & 1;
        if (kt + 1 < NK) { load_tile(buf ^ 1, kt + 1); cp_commit(); cp_wait1(); }
        else            { cp_wait0(); }
        __syncthreads();
        compute(buf);
        __syncthreads();
    }

    const int g = lane >> 2, t = lane & 3;
    #pragma unroll
    for (int mt = 0; mt < 2; mt++) {
        #pragma unroll
        for (int nt = 0; nt < 8; nt++) {
            const int col = bn + warp_n * 64 + nt * 8 + 2 * t;
            #pragma unroll
            for (int half = 0; half < 2; half++) {
                const int r = bm + warp_m * 32 + mt * 16 + g + half * 8;
                float v0 = acc[mt][nt][half * 2 + 0];
                float v1 = acc[mt][nt][half * 2 + 1];
                if (BIAS) { v0 += bias[col]; v1 += bias[col + 1]; }
                if (GELU) { v0 = gelu_exact(v0); v1 = gelu_exact(v1); }
                if (RES) {
                    const float* rp = res + (size_t)r * Ni + col;
                    v0 += rp[0]; v1 += rp[1];
                }
                if (OUTMODE == 0) {
                    float2 o; o.x = v0; o.y = v1;
                    *(float2*)((float*)Cout + (size_t)r * Ni + col) = o;
                } else {
                    __nv_bfloat162 hh, ll;
                    split2(v0, v1, hh, ll);
                    __nv_bfloat16* Cb = (__nv_bfloat16*)Cout;
                    size_t base = (size_t)r * (3 * Ni) + col;
                    *(__nv_bfloat162*)(Cb + base)          = hh;
                    *(__nv_bfloat162*)(Cb + base + Ni)     = hh;
                    *(__nv_bfloat162*)(Cb + base + 2 * Ni) = ll;
                }
            }
        }
    }
}

// ---------------------------------------------------------------------------
// Tensor-core causal flash attention (bf16x3 split, fp32 softmax).
// Block: 128 threads (4 warps), 64 queries per block. Grid: (S/64, B*H).
// Each warp owns 16 query rows. K/V tiles 64x64 staged as hi/lo bf16 in
// swizzled smem; QK and PV via mma.sync m16n8k16 with 3-product splits.
// Output written in expanded [hi|hi|lo] bf16 layout for the WO GEMM.
// ---------------------------------------------------------------------------
__global__ __launch_bounds__(128)
void attn_mma_kernel(const float* __restrict__ Q, const float* __restrict__ K,
                     const float* __restrict__ V, __nv_bfloat16* __restrict__ O)
{
    const int qt  = (gridDim.x - 1) - blockIdx.x;  // long blocks first
    const int bh  = blockIdx.y;
    const int b   = bh >> 4;
    const int h   = bh & 15;
    const int tid = threadIdx.x;
    const int w   = tid >> 5;
    const int lane = tid & 31;
    const int g   = lane >> 2;   // 0..7
    const int t4  = lane & 3;    // 0..3
    const int l7  = lane & 7;

    __shared__ __align__(128) __nv_bfloat16 sKh[64 * 64];
    __shared__ __align__(128) __nv_bfloat16 sKl[64 * 64];
    __shared__ __align__(128) __nv_bfloat16 sVh[64 * 64];
    __shared__ __align__(128) __nv_bfloat16 sVl[64 * 64];
    const uint32_t aKh = (uint32_t)__cvta_generic_to_shared(sKh);
    const uint32_t aKl = (uint32_t)__cvta_generic_to_shared(sKl);
    const uint32_t aVh = (uint32_t)__cvta_generic_to_shared(sVh);
    const uint32_t aVl = (uint32_t)__cvta_generic_to_shared(sVl);

    // ---- load Q fragments (per warp: rows w*16 .. +16), pre-scaled, split ----
    unsigned qh[4][4], ql[4][4];
    {
        const float* Qw = Q + ((size_t)(b * Sz + qt * 64 + w * 16)) * Dz + h * DKz;
        #pragma unroll
        for (int ko = 0; ko < 4; ko++) {
            #pragma unroll
            for (int rh = 0; rh < 2; rh++) {
                const float* rp = Qw + (size_t)(rh * 8 + g) * Dz + ko * 16 + 2 * t4;
                float2 lo = *(const float2*)rp;
                float2 hi = *(const float2*)(rp + 8);
                split_pack(lo.x * 0.125f, lo.y * 0.125f, qh[ko][rh],     ql[ko][rh]);
                split_pack(hi.x * 0.125f, hi.y * 0.125f, qh[ko][2 + rh], ql[ko][2 + rh]);
            }
        }
    }

    float out[8][4];
    #pragma unroll
    for (int nd = 0; nd < 8; nd++)
        #pragma unroll
        for (int i = 0; i < 4; i++) out[nd][i] = 0.f;
    float m0 = -1e30f, m1 = -1e30f, l0 = 0.f, l1 = 0.f;

    const float* Kb = K + ((size_t)(b * Sz)) * Dz + h * DKz;
    const float* Vb = V + ((size_t)(b * Sz)) * Dz + h * DKz;

    for (int kt = 0; kt <= qt; kt++) {
        __syncthreads();  // previous tile fully consumed
        // ---- stage K/V tile: fp32 -> split bf16, swizzled smem ----
        const float* Kt = Kb + (size_t)kt * 64 * Dz;
        const float* Vt = Vb + (size_t)kt * 64 * Dz;
        #pragma unroll
        for (int i = 0; i < 8; i++) {
            int idx = i * 128 + tid;
            int row = idx >> 4, c4 = idx & 15;
            float4 kv = *(const float4*)(Kt + (size_t)row * Dz + c4 * 4);
            float4 vv = *(const float4*)(Vt + (size_t)row * Dz + c4 * 4);
            uint32_t off = (row << 7) + ((((c4 >> 1) ^ (row & 7)) << 4)) + ((c4 & 1) << 3);
            unsigned h0, h1, e0, e1;
            split_pack(kv.x, kv.y, h0, e0);
            split_pack(kv.z, kv.w, h1, e1);
            *(uint2*)((char*)sKh + off) = make_uint2(h0, h1);
            *(uint2*)((char*)sKl + off) = make_uint2(e0, e1);
            split_pack(vv.x, vv.y, h0, e0);
            split_pack(vv.z, vv.w, h1, e1);
            *(uint2*)((char*)sVh + off) = make_uint2(h0, h1);
            *(uint2*)((char*)sVl + off) = make_uint2(e0, e1);
        }
        __syncthreads();

        // ---- QK^T: s = Qh*Kh + Qh*Kl + Ql*Kh ----
        float s[8][4];
        #pragma unroll
        for (int nd = 0; nd < 8; nd++)
            #pragma unroll
            for (int i = 0; i < 4; i++) s[nd][i] = 0.f;

        #pragma unroll
        for (int ko = 0; ko < 4; ko++) {
            #pragma unroll
            for (int nd2 = 0; nd2 < 4; nd2++) {
                int row = nd2 * 16 + l7 + ((lane >> 4) << 3);       // key row
                int ch  = 2 * ko + ((lane >> 3) & 1);               // dk 16B chunk
                uint32_t ad = (uint32_t)((row << 7) + ((ch ^ (row & 7)) << 4));
                unsigned rkh[4], rkl[4];
                ldsm_x4(rkh, aKh + ad);
                ldsm_x4(rkl, aKl + ad);
                mma_bf16(s[2 * nd2],     qh[ko], &rkh[0], s[2 * nd2]);
                mma_bf16(s[2 * nd2],     qh[ko], &rkl[0], s[2 * nd2]);
                mma_bf16(s[2 * nd2],     ql[ko], &rkh[0], s[2 * nd2]);
                mma_bf16(s[2 * nd2 + 1], qh[ko], &rkh[2], s[2 * nd2 + 1]);
                mma_bf16(s[2 * nd2 + 1], qh[ko], &rkl[2], s[2 * nd2 + 1]);
                mma_bf16(s[2 * nd2 + 1], ql[ko], &rkh[2], s[2 * nd2 + 1]);
            }
        }

        // ---- causal mask on diagonal tile ----
        if (kt == qt) {
            const int r0 = w * 16 + g;
            const int r1 = r0 + 8;
            #pragma unroll
            for (int nd = 0; nd < 8; nd++) {
                int c0 = nd * 8 + 2 * t4;
                if (c0 > r0)     s[nd][0] = -1e30f;
                if (c0 + 1 > r0) s[nd][1] = -1e30f;
                if (c0 > r1)     s[nd][2] = -1e30f;
                if (c0 + 1 > r1) s[nd][3] = -1e30f;
            }
        }

        // ---- online softmax (rows g and g+8) ----
        float mx0 = -1e30f, mx1 = -1e30f;
        #pragma unroll
        for (int nd = 0; nd < 8; nd++) {
            mx0 = fmaxf(mx0, fmaxf(s[nd][0], s[nd][1]));
            mx1 = fmaxf(mx1, fmaxf(s[nd][2], s[nd][3]));
        }
        mx0 = fmaxf(mx0, __shfl_xor_sync(0xffffffffu, mx0, 1));
        mx0 = fmaxf(mx0, __shfl_xor_sync(0xffffffffu, mx0, 2));
        mx1 = fmaxf(mx1, __shfl_xor_sync(0xffffffffu, mx1, 1));
        mx1 = fmaxf(mx1, __shfl_xor_sync(0xffffffffu, mx1, 2));
        float mn0 = fmaxf(m0, mx0), mn1 = fmaxf(m1, mx1);
        float c0 = __expf(m0 - mn0), c1 = __expf(m1 - mn1);
        m0 = mn0; m1 = mn1;
        l0 *= c0;  l1 *= c1;
        #pragma unroll
        for (int nd = 0; nd < 8; nd++) {
            out[nd][0] *= c0; out[nd][1] *= c0;
            out[nd][2] *= c1; out[nd][3] *= c1;
        }

        // ---- p = exp(s-m), split into bf16 A-fragments (register repack) ----
        unsigned ph[4][4], pl[4][4];
        #pragma unroll
        for (int nd = 0; nd < 8; nd++) {
            float p0 = __expf(s[nd][0] - m0);
            float p1 = __expf(s[nd][1] - m0);
            float p2 = __expf(s[nd][2] - m1);
            float p3 = __expf(s[nd][3] - m1);
            l0 += p0 + p1;
            l1 += p2 + p3;
            const int ko = nd >> 1, rr = (nd & 1) * 2;
            split_pack(p0, p1, ph[ko][rr],     pl[ko][rr]);
            split_pack(p2, p3, ph[ko][rr + 1], pl[ko][rr + 1]);
        }

        // ---- PV: out += Ph*Vh + Ph*Vl + Pl*Vh (ldmatrix.trans on [key][d]) ----
        #pragma unroll
        for (int ko = 0; ko < 4; ko++) {
            #pragma unroll
            for (int nd2 = 0; nd2 < 4; nd2++) {
                int row = ko * 16 + l7 + (((lane >> 3) & 1) << 3);  // key row
                int ch  = 2 * nd2 + (lane >> 4);                    // d 16B chunk
                uint32_t ad = (uint32_t)((row << 7) + ((ch ^ (row & 7)) << 4));
                unsigned rvh[4], rvl[4];
                ldsm_x4_t(rvh, aVh + ad);
                ldsm_x4_t(rvl, aVl + ad);
                mma_bf16(out[2 * nd2],     ph[ko], &rvh[0], out[2 * nd2]);
                mma_bf16(out[2 * nd2],     ph[ko], &rvl[0], out[2 * nd2]);
                mma_bf16(out[2 * nd2],     pl[ko], &rvh[0], out[2 * nd2]);
                mma_bf16(out[2 * nd2 + 1], ph[ko], &rvh[2], out[2 * nd2 + 1]);
                mma_bf16(out[2 * nd2 + 1], ph[ko], &rvl[2], out[2 * nd2 + 1]);
                mma_bf16(out[2 * nd2 + 1], pl[ko], &rvh[2], out[2 * nd2 + 1]);
            }
        }
    }

    // ---- epilogue: reduce l across quad, normalize, write expanded bf16 ----
    l0 += __shfl_xor_sync(0xffffffffu, l0, 1);
    l0 += __shfl_xor_sync(0xffffffffu, l0, 2);
    l1 += __shfl_xor_sync(0xffffffffu, l1, 1);
    l1 += __shfl_xor_sync(0xffffffffu, l1, 2);
    const float i0 = 1.0f / l0, i1 = 1.0f / l1;

    const size_t r0 = (size_t)(b * Sz + qt * 64 + w * 16 + g);
    const size_t r1 = r0 + 8;
    #pragma unroll
    for (int nd = 0; nd < 8; nd++) {
        const int col = h * DKz + nd * 8 + 2 * t4;
        {
            float v0 = out[nd][0] * i0, v1 = out[nd][1] * i0;
            __nv_bfloat162 hh, ll;
            split2(v0, v1, hh, ll);
            __nv_bfloat16* p = O + r0 * (3 * Dz) + col;
            *(__nv_bfloat162*)(p)          = hh;
            *(__nv_bfloat162*)(p + Dz)     = hh;
            *(__nv_bfloat162*)(p + 2 * Dz) = ll;
        }
        {
            float v0 = out[nd][2] * i1, v1 = out[nd][3] * i1;
            __nv_bfloat162 hh, ll;
            split2(v0, v1, hh, ll);
            __nv_bfloat16* p = O + r1 * (3 * Dz) + col;
            *(__nv_bfloat162*)(p)          = hh;
            *(__nv_bfloat162*)(p + Dz)     = hh;
            *(__nv_bfloat162*)(p + 2 * Dz) = ll;
        }
    }
}

// ---------------------------------------------------------------------------
// Launcher
// ---------------------------------------------------------------------------
extern "C" void kernel_launch(void* const* d_in, const int* in_sizes, int n_in,
                              void* d_out, int out_size)
{
    (void)in_sizes; (void)n_in; (void)out_size;

    const float* x   = (const float*)d_in[0];
    const float* wq  = (const float*)d_in[1];
    const float* wk  = (const float*)d_in[2];
    const float* wv  = (const float*)d_in[3];
    const float* wo  = (const float*)d_in[4];
    const float* bo  = (const float*)d_in[5];
    const float* w1  = (const float*)d_in[6];
    const float* b1  = (const float*)d_in[7];
    const float* w2  = (const float*)d_in[8];
    const float* b2  = (const float*)d_in[9];
    const float* g1  = (const float*)d_in[10];
    const float* be1 = (const float*)d_in[11];
    const float* g2  = (const float*)d_in[12];
    const float* be2 = (const float*)d_in[13];
    float* out = (float*)d_out;

    __nv_bfloat16 *h1x, *atx, *h2x, *f1x, *wqx, *wkx, *wvx, *wox, *w1x, *w2x;
    float *q, *k, *v, *x2;
    cudaGetSymbolAddress((void**)&h1x, g_h1x);
    cudaGetSymbolAddress((void**)&q,   g_q);
    cudaGetSymbolAddress((void**)&k,   g_k);
    cudaGetSymbolAddress((void**)&v,   g_v);
    cudaGetSymbolAddress((void**)&atx, g_atx);
    cudaGetSymbolAddress((void**)&x2,  g_x2);
    cudaGetSymbolAddress((void**)&h2x, g_h2x);
    cudaGetSymbolAddress((void**)&f1x, g_f1x);
    cudaGetSymbolAddress((void**)&wqx, g_wqx);
    cudaGetSymbolAddress((void**)&wkx, g_wkx);
    cudaGetSymbolAddress((void**)&wvx, g_wvx);
    cudaGetSymbolAddress((void**)&wox, g_wox);
    cudaGetSymbolAddress((void**)&w1x, g_w1x);
    cudaGetSymbolAddress((void**)&w2x, g_w2x);

    // expand weights to bf16x3
    {
        int nDD  = (Dz * Dz) / 4;
        int nDF  = (Dz * DFFz) / 4;
        wexpand_kernel<<<(nDD + 255) / 256, 256>>>(wq, wqx, Dz, Dz);
        wexpand_kernel<<<(nDD + 255) / 256, 256>>>(wk, wkx, Dz, Dz);
        wexpand_kernel<<<(nDD + 255) / 256, 256>>>(wv, wvx, Dz, Dz);
        wexpand_kernel<<<(nDD + 255) / 256, 256>>>(wo, wox, Dz, Dz);
        wexpand_kernel<<<(nDF + 255) / 256, 256>>>(w1, w1x, Dz, DFFz);
        wexpand_kernel<<<(nDF + 255) / 256, 256>>>(w2, w2x, DFFz, Dz);
    }

    const dim3 blk(256);
    const dim3 gD(Dz / 128, Mz / 128);    // (8, 64)
    const dim3 gF(DFFz / 128, Mz / 128);  // (32, 64)
    const int KD = 3 * Dz;    // 3072
    const int KF = 3 * DFFz;  // 12288

    ln_expand_kernel<<<Mz, 256>>>(x, g1, be1, h1x);
    gemm_bf16<0, false, false, false><<<gD, blk>>>(h1x, wqx, nullptr, nullptr, q, Mz, Dz, KD);
    gemm_bf16<0, false, false, false><<<gD, blk>>>(h1x, wkx, nullptr, nullptr, k, Mz, Dz, KD);
    gemm_bf16<0, false, false, false><<<gD, blk>>>(h1x, wvx, nullptr, nullptr, v, Mz, Dz, KD);
    attn_mma_kernel<<<dim3(Sz / 64, Bz * Hz), 128>>>(q, k, v, atx);
    gemm_bf16<0, false, true, true><<<gD, blk>>>(atx, wox, bo, x, x2, Mz, Dz, KD);
    ln_expand_kernel<<<Mz, 256>>>(x2, g2, be2, h2x);
    gemm_bf16<1, true, true, false><<<gF, blk>>>(h2x, w1x, b1, nullptr, f1x, Mz, DFFz, KD);
    gemm_bf16<0, false, true, true><<<gD, blk>>>(f1x, w2x, b2, x2, out, Mz, Dz, KF);
}